// round 8
// baseline (speedup 1.0000x reference)
#include <cuda_runtime.h>
#include <math.h>
#include <stdint.h>

// Problem constants
#define B_    4
#define N_    1024
#define DIM_  768
#define H_    12
#define KV_   4
#define D_    64
#define SIDE_ 32
#define WIN_  8
#define REP_  (H_ / KV_)       // 3
#define M_ROWS (B_ * N_)       // 4096

// Fused projection layout: [row][2560] = q(0..1535) | k(1536..2047) | v1(2048..2303) | v2(2304..2559)
#define PROJ_N 2560
#define OFF_K  1536
#define OFF_V1 2048

// ---------------------------------------------------------------------------
// Scratch
// ---------------------------------------------------------------------------
__device__ float g_x   [M_ROWS * DIM_];
__device__ float g_wqkv[PROJ_N * DIM_];
__device__ float g_wo  [DIM_ * DIM_];
__device__ float g_proj[M_ROWS * PROJ_N];
__device__ float g_ctx [M_ROWS * DIM_];

// ---------------------------------------------------------------------------
// PTX helpers
// ---------------------------------------------------------------------------
__device__ __forceinline__ float to_tf32(float x) {
    asm("cvt.rna.tf32.f32 %0, %0;" : "+f"(x));
    return x;
}
__device__ __forceinline__ uint32_t f2tf(float x) {
    asm("cvt.rna.tf32.f32 %0, %0;" : "+f"(x));
    return __float_as_uint(x);
}
__device__ __forceinline__ void mma_tf32(float* c, const uint32_t* a, const uint32_t* b) {
    asm volatile(
        "mma.sync.aligned.m16n8k8.row.col.f32.tf32.tf32.f32 "
        "{%0,%1,%2,%3}, {%4,%5,%6,%7}, {%8,%9}, {%0,%1,%2,%3};\n"
        : "+f"(c[0]), "+f"(c[1]), "+f"(c[2]), "+f"(c[3])
        : "r"(a[0]), "r"(a[1]), "r"(a[2]), "r"(a[3]), "r"(b[0]), "r"(b[1]));
}
__device__ __forceinline__ void cpa16(float* dst, const float* src) {
    unsigned u = (unsigned)__cvta_generic_to_shared(dst);
    asm volatile("cp.async.cg.shared.global [%0], [%1], 16;\n" :: "r"(u), "l"(src));
}

// ---------------------------------------------------------------------------
// Prep: tf32-round x, concat+round weights (float4 per thread).
// ---------------------------------------------------------------------------
#define PREP_TOTAL 1425408

__global__ __launch_bounds__(256)
void prep_tf32(const float* __restrict__ x,  const float* __restrict__ Wq,
               const float* __restrict__ Wk, const float* __restrict__ Wv1,
               const float* __restrict__ Wv2,const float* __restrict__ Wo)
{
    int idx = blockIdx.x * 256 + threadIdx.x;
    if (idx >= PREP_TOTAL) return;

    const float4* src;
    float4* dst;
    if (idx < 786432)        { src = (const float4*)x   + idx;           dst = (float4*)g_x    + idx; }
    else if (idx < 1081344)  { int i = idx - 786432;  src = (const float4*)Wq  + i; dst = (float4*)g_wqkv + i; }
    else if (idx < 1179648)  { int i = idx - 1081344; src = (const float4*)Wk  + i; dst = (float4*)g_wqkv + 294912 + i; }
    else if (idx < 1228800)  { int i = idx - 1179648; src = (const float4*)Wv1 + i; dst = (float4*)g_wqkv + 393216 + i; }
    else if (idx < 1277952)  { int i = idx - 1228800; src = (const float4*)Wv2 + i; dst = (float4*)g_wqkv + 442368 + i; }
    else                     { int i = idx - 1277952; src = (const float4*)Wo  + i; dst = (float4*)g_wo   + i; }

    float4 v = *src;
    v.x = to_tf32(v.x); v.y = to_tf32(v.y);
    v.z = to_tf32(v.z); v.w = to_tf32(v.w);
    *dst = v;
}

// ---------------------------------------------------------------------------
// TF32 tensor-core GEMM (pre-rounded inputs). 256x128 block tile, TBK=32,
// 8 warps as 4(M)x2(N) -> 64x64 warp tile (1.0 LDS per MMA), 3-stage cp.async.
// Epilogue tf32-rounds output columns n >= round_col.
// ---------------------------------------------------------------------------
#define TBM 256
#define TBN 128
#define TBK 32
#define GPAD 36
#define GSTG 3
#define GEMM_SMEM_BYTES (GSTG * (TBM + TBN) * GPAD * 4)   // 165888

__global__ __launch_bounds__(256)
void gemm_tf32(const float* __restrict__ A, const float* __restrict__ W,
               const float* __restrict__ bias, float* __restrict__ C,
               int M, int N, int K, int round_col)
{
    extern __shared__ float sm[];
    float* As = sm;                         // [GSTG][256][36]
    float* Ws = sm + GSTG * TBM * GPAD;     // [GSTG][128][36]

    const int tid  = threadIdx.x;
    const int lane = tid & 31;
    const int warp = tid >> 5;
    const int wm   = (warp & 3) * 64;       // 4 m-warps
    const int wn   = (warp >> 2) * 64;      // 2 n-warps
    const int gid  = lane >> 2;
    const int tig  = lane & 3;

    const int m0 = blockIdx.y * TBM;
    const int n0 = blockIdx.x * TBN;
    const bool roundv = (n0 >= round_col);

    // loader: A = 2048 f4 chunks, B = 1024; 12 per thread
    auto load_stage = [&](int st, int k0) {
#pragma unroll
        for (int i = 0; i < 12; i++) {
            int idx = tid + i * 256;
            if (idx < 2048) {
                int r = idx >> 3, c = (idx & 7) * 4;
                cpa16(As + (st * TBM + r) * GPAD + c, A + (size_t)(m0 + r) * K + k0 + c);
            } else {
                int j = idx - 2048;
                int r = j >> 3, c = (j & 7) * 4;
                cpa16(Ws + (st * TBN + r) * GPAD + c, W + (size_t)(n0 + r) * K + k0 + c);
            }
        }
        asm volatile("cp.async.commit_group;\n" ::: "memory");
    };

    float acc[4][8][4];
#pragma unroll
    for (int i = 0; i < 4; i++)
#pragma unroll
        for (int j = 0; j < 8; j++)
#pragma unroll
            for (int l = 0; l < 4; l++) acc[i][j][l] = 0.f;

    const int nkt = K / TBK;
    load_stage(0, 0);
    if (nkt > 1) load_stage(1, TBK);

    for (int kt = 0; kt < nkt; kt++) {
        const int cur = kt % GSTG;
        if (kt + 1 < nkt) {
            asm volatile("cp.async.wait_group 1;\n" ::: "memory");
        } else {
            asm volatile("cp.async.wait_group 0;\n" ::: "memory");
        }
        __syncthreads();
        if (kt + 2 < nkt) load_stage((kt + 2) % GSTG, (kt + 2) * TBK);

        const float* Ab = As + cur * TBM * GPAD;
        const float* Wb = Ws + cur * TBN * GPAD;

#pragma unroll
        for (int ks = 0; ks < 4; ks++) {
            const int kk = ks * 8;
            uint32_t bfr[8][2];
#pragma unroll
            for (int nt = 0; nt < 8; nt++) {
                int n = wn + nt * 8 + gid;
                bfr[nt][0] = __float_as_uint(Wb[n * GPAD + kk + tig]);
                bfr[nt][1] = __float_as_uint(Wb[n * GPAD + kk + tig + 4]);
            }
#pragma unroll
            for (int mt = 0; mt < 4; mt++) {
                int m = wm + mt * 16 + gid;
                uint32_t af[4];
                af[0] = __float_as_uint(Ab[m * GPAD + kk + tig]);
                af[1] = __float_as_uint(Ab[(m + 8) * GPAD + kk + tig]);
                af[2] = __float_as_uint(Ab[m * GPAD + kk + tig + 4]);
                af[3] = __float_as_uint(Ab[(m + 8) * GPAD + kk + tig + 4]);
#pragma unroll
                for (int nt = 0; nt < 8; nt++)
                    mma_tf32(acc[mt][nt], af, bfr[nt]);
            }
        }
        __syncthreads();
    }

#pragma unroll
    for (int mt = 0; mt < 4; mt++) {
        int m = m0 + wm + mt * 16 + gid;
#pragma unroll
        for (int nt = 0; nt < 8; nt++) {
            int n = n0 + wn + nt * 8 + 2 * tig;
            float b0 = bias ? bias[n] : 0.f;
            float b1 = bias ? bias[n + 1] : 0.f;
            float2 r0 = make_float2(acc[mt][nt][0] + b0, acc[mt][nt][1] + b1);
            float2 r1 = make_float2(acc[mt][nt][2] + b0, acc[mt][nt][3] + b1);
            if (roundv) {
                r0.x = to_tf32(r0.x); r0.y = to_tf32(r0.y);
                r1.x = to_tf32(r1.x); r1.y = to_tf32(r1.y);
            }
            *reinterpret_cast<float2*>(C + (size_t)m * N + n) = r0;
            *reinterpret_cast<float2*>(C + (size_t)(m + 8) * N + n) = r1;
        }
    }
}

// ---------------------------------------------------------------------------
// 2D RoPE + qk-norm (one warp per 64-vector). tf32-rounded output.
// ---------------------------------------------------------------------------
__global__ __launch_bounds__(256)
void rope_norm(float* __restrict__ buf, int vpr, int stride, int total_vec)
{
    const int gw   = (blockIdx.x * blockDim.x + threadIdx.x) >> 5;
    const int lane = threadIdx.x & 31;
    if (gw >= total_vec) return;

    const int row = gw / vpr;
    const int vec = gw - row * vpr;
    const int n   = row & (N_ - 1);
    const float ph = (float)(n >> 5);
    const float pw = (float)(n & 31);

    float* p = buf + (size_t)row * stride + vec * 64;
    float x0 = p[lane];
    float x1 = p[lane + 32];

    float inv = exp2f((float)lane * -0.4152410118609203f);
    float t0 = ph * inv, t1 = pw * inv;
    float c0, s0, c1, s1;
    __sincosf(t0, &s0, &c0);
    __sincosf(t1, &s1, &c1);

    float px0 = __shfl_xor_sync(0xffffffffu, x0, 1);
    float px1 = __shfl_xor_sync(0xffffffffu, x1, 1);
    float r0 = (lane & 1) ? px0 : -px0;
    float r1 = (lane & 1) ? px1 : -px1;

    float o0 = x0 * c0 + r0 * s0;
    float o1 = x1 * c1 + r1 * s1;

    float ss = o0 * o0 + o1 * o1;
#pragma unroll
    for (int o = 16; o; o >>= 1) ss += __shfl_xor_sync(0xffffffffu, ss, o);
    float sc = 1.f / (sqrtf(ss) + 1e-6f);

    p[lane]      = to_tf32(o0 * sc);
    p[lane + 32] = to_tf32(o1 * sc);
}

// ---------------------------------------------------------------------------
// Tensor-core windowed differential attention, no online softmax,
// 64-key tiles (2 grid rows per iteration -> 9 iterations max).
// Block = (b, kh, ph): 512 blocks, 6 warps. Warp = (side, head).
// smem: sKV [2][4][64][68] = 34816 fl; sP [6][32][68] = 13056 fl. 191488 B.
// ---------------------------------------------------------------------------
#define ATT_SMEM_FLOATS (34816 + 13056)
#define ATT_SMEM_BYTES  (ATT_SMEM_FLOATS * 4)

__global__ __launch_bounds__(192)
void attn_tc(const float* __restrict__ lambda_p)
{
    extern __shared__ float sm[];
    float* sKV = sm;            // [2][4][64][68]
    float* sP  = sm + 34816;    // [6][32][68]

    const int tid  = threadIdx.x;
    const int lane = tid & 31;
    const int warp = tid >> 5;
    const int gid  = lane >> 2;
    const int tig  = lane & 3;

    const int blk = blockIdx.x;
    const int ph  = blk & 31;
    const int kh  = (blk >> 5) & 3;
    const int b   = blk >> 7;

    const int side = warp / 3;
    const int hloc = warp - side * 3;
    const int h    = kh * 3 + hloc;

    const int rlo = max(ph - WIN_, 0);
    const int rhi = min(ph + WIN_, SIDE_ - 1);
    const int nit = rhi - rlo + 1;
    const int npair = (nit + 1) >> 1;

    // stage loader: 4 arrays x 64 keys x 16 f4 = 4096 chunks over 192 threads
    auto load_stage = [&](int st, int rbase) {
#pragma unroll
        for (int i = 0; i < 22; i++) {
            int idx = tid + i * 192;
            if (idx < 4096) {
                int arr = idx >> 10;          // 0..3
                int key = (idx >> 4) & 63;    // 0..63
                int f4  = (idx & 15) * 4;
                int r = rbase + (key >> 5);
                if (r > rhi) r = rhi;         // clamp; masked later
                const float* src = g_proj + (size_t)(b * N_ + r * 32 + (key & 31)) * PROJ_N
                                 + OFF_K + arr * 256 + kh * 64 + f4;
                cpa16(sKV + ((size_t)(st * 4 + arr) * 64 + key) * 68 + f4, src);
            }
        }
        asm volatile("cp.async.commit_group;\n" ::: "memory");
    };

    load_stage(0, rlo);

    // Q fragments (already tf32)
    uint32_t qf[2][8][4];
    {
        const float* qb = g_proj + ((size_t)(b * N_ + ph * 32)) * PROJ_N + side * 768 + h * 64;
#pragma unroll
        for (int mt = 0; mt < 2; mt++) {
            const float* q0 = qb + (size_t)(mt * 16 + gid) * PROJ_N;
            const float* q1 = q0 + (size_t)8 * PROJ_N;
#pragma unroll
            for (int kt = 0; kt < 8; kt++) {
                qf[mt][kt][0] = __float_as_uint(q0[kt * 8 + tig]);
                qf[mt][kt][1] = __float_as_uint(q1[kt * 8 + tig]);
                qf[mt][kt][2] = __float_as_uint(q0[kt * 8 + tig + 4]);
                qf[mt][kt][3] = __float_as_uint(q1[kt * 8 + tig + 4]);
            }
        }
    }

    float o[2][8][4];
#pragma unroll
    for (int mt = 0; mt < 2; mt++)
#pragma unroll
        for (int nt = 0; nt < 8; nt++)
#pragma unroll
            for (int c = 0; c < 4; c++) o[mt][nt][c] = 0.f;

    float l_[2][2] = {{0.f, 0.f}, {0.f, 0.f}};

    float* sPw = sP + warp * 2176;       // [32][68]

    asm volatile("cp.async.wait_group 0;\n" ::: "memory");
    __syncthreads();

    for (int it = 0; it < npair; it++) {
        const int cur = it & 1;
        if (it + 1 < npair) load_stage(cur ^ 1, rlo + 2 * (it + 1));

        const float* Kb = sKV + (size_t)(cur * 4 + side) * 64 * 68;
        const float* Vb = sKV + (size_t)(cur * 4 + 2 + side) * 64 * 68;
        const int rA = rlo + 2 * it;

        // ---- two 32-key halves: S, mask+exp, P store
#pragma unroll
        for (int h2 = 0; h2 < 2; h2++) {
            const bool valid = (rA + h2) <= rhi;
            const float* Kh = Kb + h2 * 32 * 68;

            float s[2][4][4];
#pragma unroll
            for (int mt = 0; mt < 2; mt++)
#pragma unroll
                for (int nt = 0; nt < 4; nt++)
#pragma unroll
                    for (int c = 0; c < 4; c++) s[mt][nt][c] = 0.f;

#pragma unroll
            for (int kt = 0; kt < 8; kt++) {
                uint32_t bf[4][2];
#pragma unroll
                for (int nt = 0; nt < 4; nt++) {
                    bf[nt][0] = __float_as_uint(Kh[(nt * 8 + gid) * 68 + kt * 8 + tig]);
                    bf[nt][1] = __float_as_uint(Kh[(nt * 8 + gid) * 68 + kt * 8 + tig + 4]);
                }
#pragma unroll
                for (int mt = 0; mt < 2; mt++)
#pragma unroll
                    for (int nt = 0; nt < 4; nt++)
                        mma_tf32(s[mt][nt], qf[mt][kt], bf[nt]);
            }

#pragma unroll
            for (int mt = 0; mt < 2; mt++)
#pragma unroll
                for (int nt = 0; nt < 4; nt++) {
                    float p[4];
#pragma unroll
                    for (int c = 0; c < 4; c++) {
                        int half = c >> 1;
                        int pwq = mt * 16 + gid + half * 8;
                        int ck = nt * 8 + 2 * tig + (c & 1);
                        int d = pwq - ck; d = (d < 0) ? -d : d;
                        p[c] = (d > WIN_ || !valid) ? 0.f : __expf(s[mt][nt][c] * 0.125f);
                    }
                    l_[mt][0] += p[0] + p[1];
                    l_[mt][1] += p[2] + p[3];
                    int r0 = mt * 16 + gid, r1 = r0 + 8;
                    int cc = h2 * 32 + nt * 8 + 2 * tig;
                    sPw[r0 * 68 + cc]     = __uint_as_float(f2tf(p[0]));
                    sPw[r0 * 68 + cc + 1] = __uint_as_float(f2tf(p[1]));
                    sPw[r1 * 68 + cc]     = __uint_as_float(f2tf(p[2]));
                    sPw[r1 * 68 + cc + 1] = __uint_as_float(f2tf(p[3]));
                }
        }
        __syncwarp();

        // ---- O += P @ V  (32 x 64, k = 64 keys -> 8 k-steps)
#pragma unroll
        for (int kt = 0; kt < 8; kt++) {
            uint32_t af[2][4];
#pragma unroll
            for (int mt = 0; mt < 2; mt++) {
                int r0 = mt * 16 + gid;
                af[mt][0] = __float_as_uint(sPw[r0 * 68 + kt * 8 + tig]);
                af[mt][1] = __float_as_uint(sPw[(r0 + 8) * 68 + kt * 8 + tig]);
                af[mt][2] = __float_as_uint(sPw[r0 * 68 + kt * 8 + tig + 4]);
                af[mt][3] = __float_as_uint(sPw[(r0 + 8) * 68 + kt * 8 + tig + 4]);
            }
#pragma unroll
            for (int nt = 0; nt < 8; nt++) {
                uint32_t bf[2];
                bf[0] = __float_as_uint(Vb[(kt * 8 + tig) * 68 + nt * 8 + gid]);
                bf[1] = __float_as_uint(Vb[(kt * 8 + tig + 4) * 68 + nt * 8 + gid]);
                mma_tf32(o[0][nt], af[0], bf);
                mma_tf32(o[1][nt], af[1], bf);
            }
        }

        asm volatile("cp.async.wait_group 0;\n" ::: "memory");
        __syncthreads();
    }

    // ---- final row-sum reduction
#pragma unroll
    for (int mt = 0; mt < 2; mt++)
#pragma unroll
        for (int hf = 0; hf < 2; hf++) {
            float r = l_[mt][hf];
            r += __shfl_xor_sync(0xffffffffu, r, 1);
            r += __shfl_xor_sync(0xffffffffu, r, 2);
            l_[mt][hf] = r;
        }

    float lam = log1pf(__expf(lambda_p[h]));
    float inv[2][2] = {{1.f / l_[0][0], 1.f / l_[0][1]},
                       {1.f / l_[1][0], 1.f / l_[1][1]}};

    __syncthreads();
    if (side == 1) {
        float* sO2 = sP + hloc * 2176;   // [32][68]
#pragma unroll
        for (int mt = 0; mt < 2; mt++)
#pragma unroll
            for (int nt = 0; nt < 8; nt++) {
                int r0 = mt * 16 + gid, r1 = r0 + 8, cc = nt * 8 + 2 * tig;
                sO2[r0 * 68 + cc]     = o[mt][nt][0] * inv[mt][0];
                sO2[r0 * 68 + cc + 1] = o[mt][nt][1] * inv[mt][0];
                sO2[r1 * 68 + cc]     = o[mt][nt][2] * inv[mt][1];
                sO2[r1 * 68 + cc + 1] = o[mt][nt][3] * inv[mt][1];
            }
    }
    __syncthreads();
    if (side == 0) {
        const float* sO2 = sP + hloc * 2176;
        float* dst = g_ctx + ((size_t)(b * N_ + ph * 32)) * 768 + h * 64;
#pragma unroll
        for (int mt = 0; mt < 2; mt++)
#pragma unroll
            for (int nt = 0; nt < 8; nt++) {
                int r0 = mt * 16 + gid, r1 = r0 + 8, cc = nt * 8 + 2 * tig;
                float2 v0, v1;
                v0.x = to_tf32(o[mt][nt][0] * inv[mt][0] - lam * sO2[r0 * 68 + cc]);
                v0.y = to_tf32(o[mt][nt][1] * inv[mt][0] - lam * sO2[r0 * 68 + cc + 1]);
                v1.x = to_tf32(o[mt][nt][2] * inv[mt][1] - lam * sO2[r1 * 68 + cc]);
                v1.y = to_tf32(o[mt][nt][3] * inv[mt][1] - lam * sO2[r1 * 68 + cc + 1]);
                *reinterpret_cast<float2*>(dst + (size_t)r0 * 768 + cc) = v0;
                *reinterpret_cast<float2*>(dst + (size_t)(r1) * 768 + cc) = v1;
            }
    }
}

// ---------------------------------------------------------------------------
// Launch
// ---------------------------------------------------------------------------
extern "C" void kernel_launch(void* const* d_in, const int* in_sizes, int n_in,
                              void* d_out, int out_size)
{
    const float* x      = (const float*)d_in[0];
    const float* Wq     = (const float*)d_in[1];
    const float* Wk     = (const float*)d_in[2];
    const float* Wv1    = (const float*)d_in[3];
    const float* Wv2    = (const float*)d_in[4];
    const float* lam_p  = (const float*)d_in[5];
    const float* Wo     = (const float*)d_in[6];
    const float* bo     = (const float*)d_in[7];
    float* out = (float*)d_out;

    float *gx, *gw, *gwo, *proj, *ctx;
    cudaGetSymbolAddress((void**)&gx,   g_x);
    cudaGetSymbolAddress((void**)&gw,   g_wqkv);
    cudaGetSymbolAddress((void**)&gwo,  g_wo);
    cudaGetSymbolAddress((void**)&proj, g_proj);
    cudaGetSymbolAddress((void**)&ctx,  g_ctx);

    cudaFuncSetAttribute(gemm_tf32, cudaFuncAttributeMaxDynamicSharedMemorySize,
                         GEMM_SMEM_BYTES);
    cudaFuncSetAttribute(attn_tc, cudaFuncAttributeMaxDynamicSharedMemorySize,
                         ATT_SMEM_BYTES);

    // tf32 pre-rounding + weight concat
    prep_tf32<<<(PREP_TOTAL + 255) / 256, 256>>>(x, Wq, Wk, Wv1, Wv2, Wo);

    // fused projections: one GEMM [4096 x 2560 x 768]; v1/v2 columns rounded
    gemm_tf32<<<dim3(PROJ_N / TBN, M_ROWS / TBM), 256, GEMM_SMEM_BYTES>>>(
        gx, gw, nullptr, proj, M_ROWS, PROJ_N, DIM_, OFF_V1);

    // RoPE + qk-norm over q+k (tf32-rounded output)
    {
        int vec = M_ROWS * 32;
        rope_norm<<<(vec * 32 + 255) / 256, 256>>>(proj, 32, PROJ_N, vec);
    }

    // tensor-core windowed differential attention (64-key tiles)
    attn_tc<<<B_ * KV_ * SIDE_, 192, ATT_SMEM_BYTES>>>(lam_p);

    // output projection + bias
    gemm_tf32<<<dim3(DIM_ / TBN, M_ROWS / TBM), 256, GEMM_SMEM_BYTES>>>(
        ctx, gwo, bo, out, M_ROWS, DIM_, DIM_, 1 << 30);
}

// round 9
// speedup vs baseline: 1.1524x; 1.1524x over previous
#include <cuda_runtime.h>
#include <math.h>
#include <stdint.h>

// Problem constants
#define B_    4
#define N_    1024
#define DIM_  768
#define H_    12
#define KV_   4
#define D_    64
#define SIDE_ 32
#define WIN_  8
#define REP_  (H_ / KV_)       // 3
#define M_ROWS (B_ * N_)       // 4096

// Fused projection layout: [row][2560] = q(0..1535) | k(1536..2047) | v1(2048..2303) | v2(2304..2559)
#define PROJ_N 2560
#define OFF_K  1536
#define OFF_V1 2048

// ---------------------------------------------------------------------------
// Scratch
// ---------------------------------------------------------------------------
__device__ float g_x   [M_ROWS * DIM_];
__device__ float g_wqkv[PROJ_N * DIM_];
__device__ float g_wo  [DIM_ * DIM_];
__device__ float g_proj[M_ROWS * PROJ_N];
__device__ float g_od  [2 * M_ROWS * DIM_];   // per-side normalized O
__device__ float g_ctx [M_ROWS * DIM_];

// ---------------------------------------------------------------------------
// PTX helpers
// ---------------------------------------------------------------------------
__device__ __forceinline__ float to_tf32(float x) {
    asm("cvt.rna.tf32.f32 %0, %0;" : "+f"(x));
    return x;
}
__device__ __forceinline__ uint32_t f2tf(float x) {
    asm("cvt.rna.tf32.f32 %0, %0;" : "+f"(x));
    return __float_as_uint(x);
}
__device__ __forceinline__ void mma_tf32(float* c, const uint32_t* a, const uint32_t* b) {
    asm volatile(
        "mma.sync.aligned.m16n8k8.row.col.f32.tf32.tf32.f32 "
        "{%0,%1,%2,%3}, {%4,%5,%6,%7}, {%8,%9}, {%0,%1,%2,%3};\n"
        : "+f"(c[0]), "+f"(c[1]), "+f"(c[2]), "+f"(c[3])
        : "r"(a[0]), "r"(a[1]), "r"(a[2]), "r"(a[3]), "r"(b[0]), "r"(b[1]));
}
__device__ __forceinline__ void cpa16(float* dst, const float* src) {
    unsigned u = (unsigned)__cvta_generic_to_shared(dst);
    asm volatile("cp.async.cg.shared.global [%0], [%1], 16;\n" :: "r"(u), "l"(src));
}

// ---------------------------------------------------------------------------
// Prep: tf32-round x, concat+round weights (float4 per thread).
// ---------------------------------------------------------------------------
#define PREP_TOTAL 1425408

__global__ __launch_bounds__(256)
void prep_tf32(const float* __restrict__ x,  const float* __restrict__ Wq,
               const float* __restrict__ Wk, const float* __restrict__ Wv1,
               const float* __restrict__ Wv2,const float* __restrict__ Wo)
{
    int idx = blockIdx.x * 256 + threadIdx.x;
    if (idx >= PREP_TOTAL) return;

    const float4* src;
    float4* dst;
    if (idx < 786432)        { src = (const float4*)x   + idx;           dst = (float4*)g_x    + idx; }
    else if (idx < 1081344)  { int i = idx - 786432;  src = (const float4*)Wq  + i; dst = (float4*)g_wqkv + i; }
    else if (idx < 1179648)  { int i = idx - 1081344; src = (const float4*)Wk  + i; dst = (float4*)g_wqkv + 294912 + i; }
    else if (idx < 1228800)  { int i = idx - 1179648; src = (const float4*)Wv1 + i; dst = (float4*)g_wqkv + 393216 + i; }
    else if (idx < 1277952)  { int i = idx - 1228800; src = (const float4*)Wv2 + i; dst = (float4*)g_wqkv + 442368 + i; }
    else                     { int i = idx - 1277952; src = (const float4*)Wo  + i; dst = (float4*)g_wo   + i; }

    float4 v = *src;
    v.x = to_tf32(v.x); v.y = to_tf32(v.y);
    v.z = to_tf32(v.z); v.w = to_tf32(v.w);
    *dst = v;
}

// ---------------------------------------------------------------------------
// TF32 tensor-core GEMM (pre-rounded inputs). 128x128 tile, cp.async 2-stage.
// (round-7 version, verbatim)
// ---------------------------------------------------------------------------
#define TBM 128
#define TBN 128
#define TBK 32
#define GPAD 36
#define GEMM_SMEM_BYTES (2 * 2 * TBM * GPAD * 4)   // 73728

__global__ __launch_bounds__(256, 2)
void gemm_tf32(const float* __restrict__ A, const float* __restrict__ W,
               const float* __restrict__ bias, float* __restrict__ C,
               int M, int N, int K, int round_col)
{
    extern __shared__ float sm[];
    float* As = sm;
    float* Ws = sm + 2 * TBM * GPAD;

    const int tid  = threadIdx.x;
    const int lane = tid & 31;
    const int warp = tid >> 5;
    const int wm   = (warp & 1) * 64;
    const int wn   = (warp >> 1) * 32;
    const int gid  = lane >> 2;
    const int tig  = lane & 3;

    const int m0 = blockIdx.y * TBM;
    const int n0 = blockIdx.x * TBN;
    const bool roundv = (n0 >= round_col);

    const int lr = tid >> 3;
    const int lc = (tid & 7) * 4;

    auto load_stage = [&](int st, int k0) {
#pragma unroll
        for (int i = 0; i < 4; i++) {
            int r = lr + 32 * i;
            cpa16(As + (st * TBM + r) * GPAD + lc, A + (size_t)(m0 + r) * K + k0 + lc);
            cpa16(Ws + (st * TBN + r) * GPAD + lc, W + (size_t)(n0 + r) * K + k0 + lc);
        }
        asm volatile("cp.async.commit_group;\n" ::: "memory");
    };

    float acc[4][4][4];
#pragma unroll
    for (int i = 0; i < 4; i++)
#pragma unroll
        for (int j = 0; j < 4; j++)
#pragma unroll
            for (int l = 0; l < 4; l++) acc[i][j][l] = 0.f;

    const int nkt = K / TBK;
    load_stage(0, 0);

    for (int kt = 0; kt < nkt; kt++) {
        const int cur = kt & 1;
        if (kt + 1 < nkt) {
            load_stage(cur ^ 1, (kt + 1) * TBK);
            asm volatile("cp.async.wait_group 1;\n" ::: "memory");
        } else {
            asm volatile("cp.async.wait_group 0;\n" ::: "memory");
        }
        __syncthreads();

        const float* Ab = As + cur * TBM * GPAD;
        const float* Wb = Ws + cur * TBN * GPAD;

#pragma unroll
        for (int ks = 0; ks < 4; ks++) {
            const int kk = ks * 8;
            uint32_t bfr[4][2];
#pragma unroll
            for (int nt = 0; nt < 4; nt++) {
                int n = wn + nt * 8 + gid;
                bfr[nt][0] = __float_as_uint(Wb[n * GPAD + kk + tig]);
                bfr[nt][1] = __float_as_uint(Wb[n * GPAD + kk + tig + 4]);
            }
#pragma unroll
            for (int mt = 0; mt < 4; mt++) {
                int m = wm + mt * 16 + gid;
                uint32_t af[4];
                af[0] = __float_as_uint(Ab[m * GPAD + kk + tig]);
                af[1] = __float_as_uint(Ab[(m + 8) * GPAD + kk + tig]);
                af[2] = __float_as_uint(Ab[m * GPAD + kk + tig + 4]);
                af[3] = __float_as_uint(Ab[(m + 8) * GPAD + kk + tig + 4]);
#pragma unroll
                for (int nt = 0; nt < 4; nt++)
                    mma_tf32(acc[mt][nt], af, bfr[nt]);
            }
        }
        __syncthreads();
    }

#pragma unroll
    for (int mt = 0; mt < 4; mt++) {
        int m = m0 + wm + mt * 16 + gid;
#pragma unroll
        for (int nt = 0; nt < 4; nt++) {
            int n = n0 + wn + nt * 8 + 2 * tig;
            float b0 = bias ? bias[n] : 0.f;
            float b1 = bias ? bias[n + 1] : 0.f;
            float2 r0 = make_float2(acc[mt][nt][0] + b0, acc[mt][nt][1] + b1);
            float2 r1 = make_float2(acc[mt][nt][2] + b0, acc[mt][nt][3] + b1);
            if (roundv) {
                r0.x = to_tf32(r0.x); r0.y = to_tf32(r0.y);
                r1.x = to_tf32(r1.x); r1.y = to_tf32(r1.y);
            }
            *reinterpret_cast<float2*>(C + (size_t)m * N + n) = r0;
            *reinterpret_cast<float2*>(C + (size_t)(m + 8) * N + n) = r1;
        }
    }
}

// ---------------------------------------------------------------------------
// 2D RoPE + qk-norm (one warp per 64-vector). tf32-rounded output.
// ---------------------------------------------------------------------------
__global__ __launch_bounds__(256)
void rope_norm(float* __restrict__ buf, int vpr, int stride, int total_vec)
{
    const int gw   = (blockIdx.x * blockDim.x + threadIdx.x) >> 5;
    const int lane = threadIdx.x & 31;
    if (gw >= total_vec) return;

    const int row = gw / vpr;
    const int vec = gw - row * vpr;
    const int n   = row & (N_ - 1);
    const float ph = (float)(n >> 5);
    const float pw = (float)(n & 31);

    float* p = buf + (size_t)row * stride + vec * 64;
    float x0 = p[lane];
    float x1 = p[lane + 32];

    float inv = exp2f((float)lane * -0.4152410118609203f);
    float t0 = ph * inv, t1 = pw * inv;
    float c0, s0, c1, s1;
    __sincosf(t0, &s0, &c0);
    __sincosf(t1, &s1, &c1);

    float px0 = __shfl_xor_sync(0xffffffffu, x0, 1);
    float px1 = __shfl_xor_sync(0xffffffffu, x1, 1);
    float r0 = (lane & 1) ? px0 : -px0;
    float r1 = (lane & 1) ? px1 : -px1;

    float o0 = x0 * c0 + r0 * s0;
    float o1 = x1 * c1 + r1 * s1;

    float ss = o0 * o0 + o1 * o1;
#pragma unroll
    for (int o = 16; o; o >>= 1) ss += __shfl_xor_sync(0xffffffffu, ss, o);
    float sc = 1.f / (sqrtf(ss) + 1e-6f);

    p[lane]      = to_tf32(o0 * sc);
    p[lane + 32] = to_tf32(o1 * sc);
}

// ---------------------------------------------------------------------------
// Tensor-core windowed attention, ONE SIDE per block (no duplication).
// Block = (b, kh, side, ph): 1024 blocks, 3 warps (96 thr). Warp = head.
// Per-warp pipeline identical to round 7: 32 queries x 64 dims, 32-key
// tiles cp.async double-buffered, no online softmax (|score| <= 0.125).
// Side 1 scales its normalized O by softplus(lambda); combine kernel
// subtracts. smem: sKV [2][2][32][68] = 8704 fl; sP [3][32][36] = 3456 fl.
// 48640 B -> 3 CTAs/SM (regs ~218*96*3 = 62.8K < 64K).
// ---------------------------------------------------------------------------
#define ATT_SMEM_FLOATS (8704 + 3456)
#define ATT_SMEM_BYTES  (ATT_SMEM_FLOATS * 4)

__global__ __launch_bounds__(96, 3)
void attn_tc(const float* __restrict__ lambda_p)
{
    extern __shared__ float sm[];
    float* sKV = sm;            // [2 stages][2 arrays: K,V][32][68]
    float* sP  = sm + 8704;     // [3][32][36]

    const int tid  = threadIdx.x;
    const int lane = tid & 31;
    const int warp = tid >> 5;           // 0..2 = head-local
    const int gid  = lane >> 2;
    const int tig  = lane & 3;

    const int blk  = blockIdx.x;         // b(4) x kh(4) x side(2) x ph(32)
    const int ph   = blk & 31;
    const int side = (blk >> 5) & 1;
    const int kh   = (blk >> 6) & 3;
    const int b    = blk >> 8;

    const int hloc = warp;
    const int h    = kh * 3 + hloc;

    const int rlo = max(ph - WIN_, 0);
    const int rhi = min(ph + WIN_, SIDE_ - 1);
    const int nit = rhi - rlo + 1;

    const int colK = OFF_K  + side * 256 + kh * 64;
    const int colV = OFF_V1 + side * 256 + kh * 64;

    // stage loader: 2 arrays x 32 keys x 16 f4 = 1024 chunks over 96 threads
    auto load_stage = [&](int st, int r) {
#pragma unroll
        for (int i = 0; i < 11; i++) {
            int idx = tid + i * 96;
            if (idx < 1024) {
                int arr = idx >> 9;           // 0 = K, 1 = V
                int key = (idx >> 4) & 31;
                int f4  = (idx & 15) * 4;
                int col = arr ? colV : colK;
                const float* src = g_proj + (size_t)(b * N_ + r * 32 + key) * PROJ_N
                                 + col + f4;
                cpa16(sKV + ((size_t)(st * 2 + arr) * 32 + key) * 68 + f4, src);
            }
        }
        asm volatile("cp.async.commit_group;\n" ::: "memory");
    };

    load_stage(0, rlo);

    // Q fragments (already tf32)
    uint32_t qf[2][8][4];
    {
        const float* qb = g_proj + ((size_t)(b * N_ + ph * 32)) * PROJ_N + side * 768 + h * 64;
#pragma unroll
        for (int mt = 0; mt < 2; mt++) {
            const float* q0 = qb + (size_t)(mt * 16 + gid) * PROJ_N;
            const float* q1 = q0 + (size_t)8 * PROJ_N;
#pragma unroll
            for (int kt = 0; kt < 8; kt++) {
                qf[mt][kt][0] = __float_as_uint(q0[kt * 8 + tig]);
                qf[mt][kt][1] = __float_as_uint(q1[kt * 8 + tig]);
                qf[mt][kt][2] = __float_as_uint(q0[kt * 8 + tig + 4]);
                qf[mt][kt][3] = __float_as_uint(q1[kt * 8 + tig + 4]);
            }
        }
    }

    float o[2][8][4];
#pragma unroll
    for (int mt = 0; mt < 2; mt++)
#pragma unroll
        for (int nt = 0; nt < 8; nt++)
#pragma unroll
            for (int c = 0; c < 4; c++) o[mt][nt][c] = 0.f;

    float l_[2][2] = {{0.f, 0.f}, {0.f, 0.f}};

    float* sPw = sP + warp * 1152;       // [32][36]

    asm volatile("cp.async.wait_group 0;\n" ::: "memory");
    __syncthreads();

    for (int it = 0; it < nit; it++) {
        const int cur = it & 1;
        if (it + 1 < nit) load_stage(cur ^ 1, rlo + it + 1);

        const float* K = sKV + (size_t)(cur * 2 + 0) * 32 * 68;
        const float* V = sKV + (size_t)(cur * 2 + 1) * 32 * 68;

        // ---- S = Q @ K^T  (32 x 32)
        float s[2][4][4];
#pragma unroll
        for (int mt = 0; mt < 2; mt++)
#pragma unroll
            for (int nt = 0; nt < 4; nt++)
#pragma unroll
                for (int c = 0; c < 4; c++) s[mt][nt][c] = 0.f;

#pragma unroll
        for (int kt = 0; kt < 8; kt++) {
            uint32_t bf[4][2];
#pragma unroll
            for (int nt = 0; nt < 4; nt++) {
                bf[nt][0] = __float_as_uint(K[(nt * 8 + gid) * 68 + kt * 8 + tig]);
                bf[nt][1] = __float_as_uint(K[(nt * 8 + gid) * 68 + kt * 8 + tig + 4]);
            }
#pragma unroll
            for (int mt = 0; mt < 2; mt++)
#pragma unroll
                for (int nt = 0; nt < 4; nt++)
                    mma_tf32(s[mt][nt], qf[mt][kt], bf[nt]);
        }

        // ---- mask + exp + P store + partial sums
        __syncwarp();
#pragma unroll
        for (int mt = 0; mt < 2; mt++)
#pragma unroll
            for (int nt = 0; nt < 4; nt++) {
                float p[4];
#pragma unroll
                for (int c = 0; c < 4; c++) {
                    int half = c >> 1;
                    int pwq = mt * 16 + gid + half * 8;
                    int ck = nt * 8 + 2 * tig + (c & 1);
                    int d = pwq - ck; d = (d < 0) ? -d : d;
                    p[c] = (d > WIN_) ? 0.f : __expf(s[mt][nt][c] * 0.125f);
                }
                l_[mt][0] += p[0] + p[1];
                l_[mt][1] += p[2] + p[3];
                int r0 = mt * 16 + gid, r1 = r0 + 8, cc = nt * 8 + 2 * tig;
                sPw[r0 * 36 + cc]     = __uint_as_float(f2tf(p[0]));
                sPw[r0 * 36 + cc + 1] = __uint_as_float(f2tf(p[1]));
                sPw[r1 * 36 + cc]     = __uint_as_float(f2tf(p[2]));
                sPw[r1 * 36 + cc + 1] = __uint_as_float(f2tf(p[3]));
            }
        __syncwarp();

        // ---- O += P @ V  (32 x 64, k = 32)
#pragma unroll
        for (int kt = 0; kt < 4; kt++) {
            uint32_t af[2][4];
#pragma unroll
            for (int mt = 0; mt < 2; mt++) {
                int r0 = mt * 16 + gid;
                af[mt][0] = __float_as_uint(sPw[r0 * 36 + kt * 8 + tig]);
                af[mt][1] = __float_as_uint(sPw[(r0 + 8) * 36 + kt * 8 + tig]);
                af[mt][2] = __float_as_uint(sPw[r0 * 36 + kt * 8 + tig + 4]);
                af[mt][3] = __float_as_uint(sPw[(r0 + 8) * 36 + kt * 8 + tig + 4]);
            }
#pragma unroll
            for (int nt = 0; nt < 8; nt++) {
                uint32_t bf[2];
                bf[0] = __float_as_uint(V[(kt * 8 + tig) * 68 + nt * 8 + gid]);
                bf[1] = __float_as_uint(V[(kt * 8 + tig + 4) * 68 + nt * 8 + gid]);
                mma_tf32(o[0][nt], af[0], bf);
                mma_tf32(o[1][nt], af[1], bf);
            }
        }

        asm volatile("cp.async.wait_group 0;\n" ::: "memory");
        __syncthreads();
    }

    // ---- final row-sum reduction
#pragma unroll
    for (int mt = 0; mt < 2; mt++)
#pragma unroll
        for (int hf = 0; hf < 2; hf++) {
            float r = l_[mt][hf];
            r += __shfl_xor_sync(0xffffffffu, r, 1);
            r += __shfl_xor_sync(0xffffffffu, r, 2);
            l_[mt][hf] = r;
        }

    // side 0: write O/l; side 1: write softplus(lambda) * O/l
    float lam = side ? log1pf(__expf(lambda_p[h])) : 1.f;
    float inv[2][2] = {{lam / l_[0][0], lam / l_[0][1]},
                       {lam / l_[1][0], lam / l_[1][1]}};

    float* dst = g_od + ((size_t)side * M_ROWS + (size_t)(b * N_ + ph * 32)) * 768 + h * 64;
#pragma unroll
    for (int mt = 0; mt < 2; mt++)
#pragma unroll
        for (int nt = 0; nt < 8; nt++) {
            int r0 = mt * 16 + gid, r1 = r0 + 8, cc = nt * 8 + 2 * tig;
            float2 v0, v1;
            v0.x = o[mt][nt][0] * inv[mt][0];
            v0.y = o[mt][nt][1] * inv[mt][0];
            v1.x = o[mt][nt][2] * inv[mt][1];
            v1.y = o[mt][nt][3] * inv[mt][1];
            *reinterpret_cast<float2*>(dst + (size_t)r0 * 768 + cc) = v0;
            *reinterpret_cast<float2*>(dst + (size_t)r1 * 768 + cc) = v1;
        }
}

// ---------------------------------------------------------------------------
// Combine: ctx = tf32(O1 - O2_scaled), float4-wide.
// ---------------------------------------------------------------------------
#define CTX_F4 (M_ROWS * DIM_ / 4)   // 786432

__global__ __launch_bounds__(256)
void combine_o()
{
    int idx = blockIdx.x * 256 + threadIdx.x;
    if (idx >= CTX_F4) return;
    const float4* o1 = reinterpret_cast<const float4*>(g_od);
    const float4* o2 = reinterpret_cast<const float4*>(g_od + (size_t)M_ROWS * DIM_);
    float4 a = o1[idx], c = o2[idx];
    float4 r;
    r.x = to_tf32(a.x - c.x);
    r.y = to_tf32(a.y - c.y);
    r.z = to_tf32(a.z - c.z);
    r.w = to_tf32(a.w - c.w);
    reinterpret_cast<float4*>(g_ctx)[idx] = r;
}

// ---------------------------------------------------------------------------
// Launch
// ---------------------------------------------------------------------------
extern "C" void kernel_launch(void* const* d_in, const int* in_sizes, int n_in,
                              void* d_out, int out_size)
{
    const float* x      = (const float*)d_in[0];
    const float* Wq     = (const float*)d_in[1];
    const float* Wk     = (const float*)d_in[2];
    const float* Wv1    = (const float*)d_in[3];
    const float* Wv2    = (const float*)d_in[4];
    const float* lam_p  = (const float*)d_in[5];
    const float* Wo     = (const float*)d_in[6];
    const float* bo     = (const float*)d_in[7];
    float* out = (float*)d_out;

    float *gx, *gw, *gwo, *proj, *ctx;
    cudaGetSymbolAddress((void**)&gx,   g_x);
    cudaGetSymbolAddress((void**)&gw,   g_wqkv);
    cudaGetSymbolAddress((void**)&gwo,  g_wo);
    cudaGetSymbolAddress((void**)&proj, g_proj);
    cudaGetSymbolAddress((void**)&ctx,  g_ctx);

    cudaFuncSetAttribute(gemm_tf32, cudaFuncAttributeMaxDynamicSharedMemorySize,
                         GEMM_SMEM_BYTES);
    cudaFuncSetAttribute(attn_tc, cudaFuncAttributeMaxDynamicSharedMemorySize,
                         ATT_SMEM_BYTES);

    // tf32 pre-rounding + weight concat
    prep_tf32<<<(PREP_TOTAL + 255) / 256, 256>>>(x, Wq, Wk, Wv1, Wv2, Wo);

    // fused projections: one GEMM [4096 x 2560 x 768]; v1/v2 columns rounded
    gemm_tf32<<<dim3(PROJ_N / TBN, M_ROWS / TBM), 256, GEMM_SMEM_BYTES>>>(
        gx, gw, nullptr, proj, M_ROWS, PROJ_N, DIM_, OFF_V1);

    // RoPE + qk-norm over q+k (tf32-rounded output)
    {
        int vec = M_ROWS * 32;
        rope_norm<<<(vec * 32 + 255) / 256, 256>>>(proj, 32, PROJ_N, vec);
    }

    // tensor-core windowed attention: one side per block, 1024 blocks
    attn_tc<<<B_ * KV_ * 2 * SIDE_, 96, ATT_SMEM_BYTES>>>(lam_p);

    // differential combine
    combine_o<<<(CTX_F4 + 255) / 256, 256>>>();

    // output projection + bias
    gemm_tf32<<<dim3(DIM_ / TBN, M_ROWS / TBM), 256, GEMM_SMEM_BYTES>>>(
        ctx, gwo, bo, out, M_ROWS, DIM_, DIM_, 1 << 30);
}

// round 10
// speedup vs baseline: 1.2115x; 1.0513x over previous
#include <cuda_runtime.h>
#include <math.h>
#include <stdint.h>

// Problem constants
#define B_    4
#define N_    1024
#define DIM_  768
#define H_    12
#define KV_   4
#define D_    64
#define SIDE_ 32
#define WIN_  8
#define REP_  (H_ / KV_)       // 3
#define M_ROWS (B_ * N_)       // 4096

// Fused projection layout: [row][2560] = q(0..1535) | k(1536..2047) | v1(2048..2303) | v2(2304..2559)
#define PROJ_N 2560
#define OFF_K  1536
#define OFF_V1 2048

// ---------------------------------------------------------------------------
// Scratch
// ---------------------------------------------------------------------------
__device__ float g_x   [M_ROWS * DIM_];
__device__ float g_wqkv[PROJ_N * DIM_];
__device__ float g_wo  [DIM_ * DIM_];
__device__ float g_proj[M_ROWS * PROJ_N];
__device__ float g_od  [2 * M_ROWS * DIM_];   // per-side normalized O
__device__ float g_ctx [M_ROWS * DIM_];

// ---------------------------------------------------------------------------
// PTX helpers
// ---------------------------------------------------------------------------
__device__ __forceinline__ float to_tf32(float x) {
    asm("cvt.rna.tf32.f32 %0, %0;" : "+f"(x));
    return x;
}
__device__ __forceinline__ uint32_t f2tf(float x) {
    asm("cvt.rna.tf32.f32 %0, %0;" : "+f"(x));
    return __float_as_uint(x);
}
__device__ __forceinline__ void mma_tf32(float* c, const uint32_t* a, const uint32_t* b) {
    asm volatile(
        "mma.sync.aligned.m16n8k8.row.col.f32.tf32.tf32.f32 "
        "{%0,%1,%2,%3}, {%4,%5,%6,%7}, {%8,%9}, {%0,%1,%2,%3};\n"
        : "+f"(c[0]), "+f"(c[1]), "+f"(c[2]), "+f"(c[3])
        : "r"(a[0]), "r"(a[1]), "r"(a[2]), "r"(a[3]), "r"(b[0]), "r"(b[1]));
}
__device__ __forceinline__ void cpa16(float* dst, const float* src) {
    unsigned u = (unsigned)__cvta_generic_to_shared(dst);
    asm volatile("cp.async.cg.shared.global [%0], [%1], 16;\n" :: "r"(u), "l"(src));
}

// ---------------------------------------------------------------------------
// Prep: tf32-round x, concat+round weights (float4 per thread).
// ---------------------------------------------------------------------------
#define PREP_TOTAL 1425408

__global__ __launch_bounds__(256)
void prep_tf32(const float* __restrict__ x,  const float* __restrict__ Wq,
               const float* __restrict__ Wk, const float* __restrict__ Wv1,
               const float* __restrict__ Wv2,const float* __restrict__ Wo)
{
    int idx = blockIdx.x * 256 + threadIdx.x;
    if (idx >= PREP_TOTAL) return;

    const float4* src;
    float4* dst;
    if (idx < 786432)        { src = (const float4*)x   + idx;           dst = (float4*)g_x    + idx; }
    else if (idx < 1081344)  { int i = idx - 786432;  src = (const float4*)Wq  + i; dst = (float4*)g_wqkv + i; }
    else if (idx < 1179648)  { int i = idx - 1081344; src = (const float4*)Wk  + i; dst = (float4*)g_wqkv + 294912 + i; }
    else if (idx < 1228800)  { int i = idx - 1179648; src = (const float4*)Wv1 + i; dst = (float4*)g_wqkv + 393216 + i; }
    else if (idx < 1277952)  { int i = idx - 1228800; src = (const float4*)Wv2 + i; dst = (float4*)g_wqkv + 442368 + i; }
    else                     { int i = idx - 1277952; src = (const float4*)Wo  + i; dst = (float4*)g_wo   + i; }

    float4 v = *src;
    v.x = to_tf32(v.x); v.y = to_tf32(v.y);
    v.z = to_tf32(v.z); v.w = to_tf32(v.w);
    *dst = v;
}

// ---------------------------------------------------------------------------
// TF32 tensor-core GEMM (pre-rounded inputs). 128x128 tile, cp.async 2-stage.
// (round-7 version, verbatim)
// ---------------------------------------------------------------------------
#define TBM 128
#define TBN 128
#define TBK 32
#define GPAD 36
#define GEMM_SMEM_BYTES (2 * 2 * TBM * GPAD * 4)   // 73728

__global__ __launch_bounds__(256, 2)
void gemm_tf32(const float* __restrict__ A, const float* __restrict__ W,
               const float* __restrict__ bias, float* __restrict__ C,
               int M, int N, int K, int round_col)
{
    extern __shared__ float sm[];
    float* As = sm;
    float* Ws = sm + 2 * TBM * GPAD;

    const int tid  = threadIdx.x;
    const int lane = tid & 31;
    const int warp = tid >> 5;
    const int wm   = (warp & 1) * 64;
    const int wn   = (warp >> 1) * 32;
    const int gid  = lane >> 2;
    const int tig  = lane & 3;

    const int m0 = blockIdx.y * TBM;
    const int n0 = blockIdx.x * TBN;
    const bool roundv = (n0 >= round_col);

    const int lr = tid >> 3;
    const int lc = (tid & 7) * 4;

    auto load_stage = [&](int st, int k0) {
#pragma unroll
        for (int i = 0; i < 4; i++) {
            int r = lr + 32 * i;
            cpa16(As + (st * TBM + r) * GPAD + lc, A + (size_t)(m0 + r) * K + k0 + lc);
            cpa16(Ws + (st * TBN + r) * GPAD + lc, W + (size_t)(n0 + r) * K + k0 + lc);
        }
        asm volatile("cp.async.commit_group;\n" ::: "memory");
    };

    float acc[4][4][4];
#pragma unroll
    for (int i = 0; i < 4; i++)
#pragma unroll
        for (int j = 0; j < 4; j++)
#pragma unroll
            for (int l = 0; l < 4; l++) acc[i][j][l] = 0.f;

    const int nkt = K / TBK;
    load_stage(0, 0);

    for (int kt = 0; kt < nkt; kt++) {
        const int cur = kt & 1;
        if (kt + 1 < nkt) {
            load_stage(cur ^ 1, (kt + 1) * TBK);
            asm volatile("cp.async.wait_group 1;\n" ::: "memory");
        } else {
            asm volatile("cp.async.wait_group 0;\n" ::: "memory");
        }
        __syncthreads();

        const float* Ab = As + cur * TBM * GPAD;
        const float* Wb = Ws + cur * TBN * GPAD;

#pragma unroll
        for (int ks = 0; ks < 4; ks++) {
            const int kk = ks * 8;
            uint32_t bfr[4][2];
#pragma unroll
            for (int nt = 0; nt < 4; nt++) {
                int n = wn + nt * 8 + gid;
                bfr[nt][0] = __float_as_uint(Wb[n * GPAD + kk + tig]);
                bfr[nt][1] = __float_as_uint(Wb[n * GPAD + kk + tig + 4]);
            }
#pragma unroll
            for (int mt = 0; mt < 4; mt++) {
                int m = wm + mt * 16 + gid;
                uint32_t af[4];
                af[0] = __float_as_uint(Ab[m * GPAD + kk + tig]);
                af[1] = __float_as_uint(Ab[(m + 8) * GPAD + kk + tig]);
                af[2] = __float_as_uint(Ab[m * GPAD + kk + tig + 4]);
                af[3] = __float_as_uint(Ab[(m + 8) * GPAD + kk + tig + 4]);
#pragma unroll
                for (int nt = 0; nt < 4; nt++)
                    mma_tf32(acc[mt][nt], af, bfr[nt]);
            }
        }
        __syncthreads();
    }

#pragma unroll
    for (int mt = 0; mt < 4; mt++) {
        int m = m0 + wm + mt * 16 + gid;
#pragma unroll
        for (int nt = 0; nt < 4; nt++) {
            int n = n0 + wn + nt * 8 + 2 * tig;
            float b0 = bias ? bias[n] : 0.f;
            float b1 = bias ? bias[n + 1] : 0.f;
            float2 r0 = make_float2(acc[mt][nt][0] + b0, acc[mt][nt][1] + b1);
            float2 r1 = make_float2(acc[mt][nt][2] + b0, acc[mt][nt][3] + b1);
            if (roundv) {
                r0.x = to_tf32(r0.x); r0.y = to_tf32(r0.y);
                r1.x = to_tf32(r1.x); r1.y = to_tf32(r1.y);
            }
            *reinterpret_cast<float2*>(C + (size_t)m * N + n) = r0;
            *reinterpret_cast<float2*>(C + (size_t)(m + 8) * N + n) = r1;
        }
    }
}

// ---------------------------------------------------------------------------
// 2D RoPE + qk-norm (one warp per 64-vector). tf32-rounded output.
// ---------------------------------------------------------------------------
__global__ __launch_bounds__(256)
void rope_norm(float* __restrict__ buf, int vpr, int stride, int total_vec)
{
    const int gw   = (blockIdx.x * blockDim.x + threadIdx.x) >> 5;
    const int lane = threadIdx.x & 31;
    if (gw >= total_vec) return;

    const int row = gw / vpr;
    const int vec = gw - row * vpr;
    const int n   = row & (N_ - 1);
    const float ph = (float)(n >> 5);
    const float pw = (float)(n & 31);

    float* p = buf + (size_t)row * stride + vec * 64;
    float x0 = p[lane];
    float x1 = p[lane + 32];

    float inv = exp2f((float)lane * -0.4152410118609203f);
    float t0 = ph * inv, t1 = pw * inv;
    float c0, s0, c1, s1;
    __sincosf(t0, &s0, &c0);
    __sincosf(t1, &s1, &c1);

    float px0 = __shfl_xor_sync(0xffffffffu, x0, 1);
    float px1 = __shfl_xor_sync(0xffffffffu, x1, 1);
    float r0 = (lane & 1) ? px0 : -px0;
    float r1 = (lane & 1) ? px1 : -px1;

    float o0 = x0 * c0 + r0 * s0;
    float o1 = x1 * c1 + r1 * s1;

    float ss = o0 * o0 + o1 * o1;
#pragma unroll
    for (int o = 16; o; o >>= 1) ss += __shfl_xor_sync(0xffffffffu, ss, o);
    float sc = 1.f / (sqrtf(ss) + 1e-6f);

    p[lane]      = to_tf32(o0 * sc);
    p[lane + 32] = to_tf32(o1 * sc);
}

// ---------------------------------------------------------------------------
// Tensor-core windowed attention, one side per block.
// Block = (b, kh, side, ph): 1024 blocks, 3 warps (96 thr). Warp = head.
// Round-10 changes vs round 9:
//   - 4 CTAs/SM (launch_bounds(96,4) + max smem carveout)
//   - window mask precomputed as a 32-bit validity mask (loop-invariant)
//   - V tile stride 72 (conflict-free LDS: bank = 8*tig+gid, all distinct)
// smem per stage: K [32][68]=2176 + V [32][72]=2304 -> 4480 fl; 2 stages
// + sP [3][32][36]=3456 fl. Total 12416 fl = 49664 B. 4 CTAs = 198.7 KB.
// ---------------------------------------------------------------------------
#define KV_STRIDE_K 68
#define KV_STRIDE_V 72
#define KV_STAGE    (32 * KV_STRIDE_K + 32 * KV_STRIDE_V)   // 4480
#define ATT_SMEM_FLOATS (2 * KV_STAGE + 3456)
#define ATT_SMEM_BYTES  (ATT_SMEM_FLOATS * 4)

__global__ __launch_bounds__(96, 4)
void attn_tc(const float* __restrict__ lambda_p)
{
    extern __shared__ float sm[];
    float* sKV = sm;                     // [2 stages][K 32x68 | V 32x72]
    float* sP  = sm + 2 * KV_STAGE;      // [3][32][36]

    const int tid  = threadIdx.x;
    const int lane = tid & 31;
    const int warp = tid >> 5;           // 0..2 = head-local
    const int gid  = lane >> 2;
    const int tig  = lane & 3;

    const int blk  = blockIdx.x;         // b(4) x kh(4) x side(2) x ph(32)
    const int ph   = blk & 31;
    const int side = (blk >> 5) & 1;
    const int kh   = (blk >> 6) & 3;
    const int b    = blk >> 8;

    const int hloc = warp;
    const int h    = kh * 3 + hloc;

    const int rlo = max(ph - WIN_, 0);
    const int rhi = min(ph + WIN_, SIDE_ - 1);
    const int nit = rhi - rlo + 1;

    const int colK = OFF_K  + side * 256 + kh * 64;
    const int colV = OFF_V1 + side * 256 + kh * 64;

    // precomputed column mask: bit (mt*16 + nt*4 + c) = |pwq - ck| <= WIN
    uint32_t mbits = 0;
#pragma unroll
    for (int mt = 0; mt < 2; mt++)
#pragma unroll
        for (int nt = 0; nt < 4; nt++)
#pragma unroll
            for (int c = 0; c < 4; c++) {
                int pwq = mt * 16 + gid + ((c >> 1) << 3);
                int ck  = nt * 8 + 2 * tig + (c & 1);
                int d = pwq - ck; d = (d < 0) ? -d : d;
                if (d <= WIN_) mbits |= 1u << (mt * 16 + nt * 4 + c);
            }

    // stage loader: 2 arrays x 32 keys x 16 f4 = 1024 chunks over 96 threads
    auto load_stage = [&](int st, int r) {
#pragma unroll
        for (int i = 0; i < 11; i++) {
            int idx = tid + i * 96;
            if (idx < 1024) {
                int arr = idx >> 9;           // 0 = K, 1 = V
                int key = (idx >> 4) & 31;
                int f4  = (idx & 15) * 4;
                int col = arr ? colV : colK;
                const float* src = g_proj + (size_t)(b * N_ + r * 32 + key) * PROJ_N
                                 + col + f4;
                float* dst = sKV + st * KV_STAGE
                           + (arr ? 32 * KV_STRIDE_K + key * KV_STRIDE_V
                                  : key * KV_STRIDE_K) + f4;
                cpa16(dst, src);
            }
        }
        asm volatile("cp.async.commit_group;\n" ::: "memory");
    };

    load_stage(0, rlo);

    // Q fragments (already tf32)
    uint32_t qf[2][8][4];
    {
        const float* qb = g_proj + ((size_t)(b * N_ + ph * 32)) * PROJ_N + side * 768 + h * 64;
#pragma unroll
        for (int mt = 0; mt < 2; mt++) {
            const float* q0 = qb + (size_t)(mt * 16 + gid) * PROJ_N;
            const float* q1 = q0 + (size_t)8 * PROJ_N;
#pragma unroll
            for (int kt = 0; kt < 8; kt++) {
                qf[mt][kt][0] = __float_as_uint(q0[kt * 8 + tig]);
                qf[mt][kt][1] = __float_as_uint(q1[kt * 8 + tig]);
                qf[mt][kt][2] = __float_as_uint(q0[kt * 8 + tig + 4]);
                qf[mt][kt][3] = __float_as_uint(q1[kt * 8 + tig + 4]);
            }
        }
    }

    float o[2][8][4];
#pragma unroll
    for (int mt = 0; mt < 2; mt++)
#pragma unroll
        for (int nt = 0; nt < 8; nt++)
#pragma unroll
            for (int c = 0; c < 4; c++) o[mt][nt][c] = 0.f;

    float l_[2][2] = {{0.f, 0.f}, {0.f, 0.f}};

    float* sPw = sP + warp * 1152;       // [32][36]

    asm volatile("cp.async.wait_group 0;\n" ::: "memory");
    __syncthreads();

    for (int it = 0; it < nit; it++) {
        const int cur = it & 1;
        if (it + 1 < nit) load_stage(cur ^ 1, rlo + it + 1);

        const float* K = sKV + cur * KV_STAGE;
        const float* V = K + 32 * KV_STRIDE_K;

        // ---- S = Q @ K^T  (32 x 32)
        float s[2][4][4];
#pragma unroll
        for (int mt = 0; mt < 2; mt++)
#pragma unroll
            for (int nt = 0; nt < 4; nt++)
#pragma unroll
                for (int c = 0; c < 4; c++) s[mt][nt][c] = 0.f;

#pragma unroll
        for (int kt = 0; kt < 8; kt++) {
            uint32_t bf[4][2];
#pragma unroll
            for (int nt = 0; nt < 4; nt++) {
                bf[nt][0] = __float_as_uint(K[(nt * 8 + gid) * KV_STRIDE_K + kt * 8 + tig]);
                bf[nt][1] = __float_as_uint(K[(nt * 8 + gid) * KV_STRIDE_K + kt * 8 + tig + 4]);
            }
#pragma unroll
            for (int mt = 0; mt < 2; mt++)
#pragma unroll
                for (int nt = 0; nt < 4; nt++)
                    mma_tf32(s[mt][nt], qf[mt][kt], bf[nt]);
        }

        // ---- masked exp + P store + partial sums
        __syncwarp();
#pragma unroll
        for (int mt = 0; mt < 2; mt++)
#pragma unroll
            for (int nt = 0; nt < 4; nt++) {
                float p[4];
#pragma unroll
                for (int c = 0; c < 4; c++) {
                    float e = __expf(s[mt][nt][c] * 0.125f);
                    p[c] = (mbits >> (mt * 16 + nt * 4 + c)) & 1 ? e : 0.f;
                }
                l_[mt][0] += p[0] + p[1];
                l_[mt][1] += p[2] + p[3];
                int r0 = mt * 16 + gid, r1 = r0 + 8, cc = nt * 8 + 2 * tig;
                sPw[r0 * 36 + cc]     = __uint_as_float(f2tf(p[0]));
                sPw[r0 * 36 + cc + 1] = __uint_as_float(f2tf(p[1]));
                sPw[r1 * 36 + cc]     = __uint_as_float(f2tf(p[2]));
                sPw[r1 * 36 + cc + 1] = __uint_as_float(f2tf(p[3]));
            }
        __syncwarp();

        // ---- O += P @ V  (32 x 64, k = 32)
#pragma unroll
        for (int kt = 0; kt < 4; kt++) {
            uint32_t af[2][4];
#pragma unroll
            for (int mt = 0; mt < 2; mt++) {
                int r0 = mt * 16 + gid;
                af[mt][0] = __float_as_uint(sPw[r0 * 36 + kt * 8 + tig]);
                af[mt][1] = __float_as_uint(sPw[(r0 + 8) * 36 + kt * 8 + tig]);
                af[mt][2] = __float_as_uint(sPw[r0 * 36 + kt * 8 + tig + 4]);
                af[mt][3] = __float_as_uint(sPw[(r0 + 8) * 36 + kt * 8 + tig + 4]);
            }
#pragma unroll
            for (int nt = 0; nt < 8; nt++) {
                uint32_t bf[2];
                bf[0] = __float_as_uint(V[(kt * 8 + tig) * KV_STRIDE_V + nt * 8 + gid]);
                bf[1] = __float_as_uint(V[(kt * 8 + tig + 4) * KV_STRIDE_V + nt * 8 + gid]);
                mma_tf32(o[0][nt], af[0], bf);
                mma_tf32(o[1][nt], af[1], bf);
            }
        }

        asm volatile("cp.async.wait_group 0;\n" ::: "memory");
        __syncthreads();
    }

    // ---- final row-sum reduction
#pragma unroll
    for (int mt = 0; mt < 2; mt++)
#pragma unroll
        for (int hf = 0; hf < 2; hf++) {
            float r = l_[mt][hf];
            r += __shfl_xor_sync(0xffffffffu, r, 1);
            r += __shfl_xor_sync(0xffffffffu, r, 2);
            l_[mt][hf] = r;
        }

    // side 0: write O/l; side 1: write softplus(lambda) * O/l
    float lam = side ? log1pf(__expf(lambda_p[h])) : 1.f;
    float inv[2][2] = {{lam / l_[0][0], lam / l_[0][1]},
                       {lam / l_[1][0], lam / l_[1][1]}};

    float* dst = g_od + ((size_t)side * M_ROWS + (size_t)(b * N_ + ph * 32)) * 768 + h * 64;
#pragma unroll
    for (int mt = 0; mt < 2; mt++)
#pragma unroll
        for (int nt = 0; nt < 8; nt++) {
            int r0 = mt * 16 + gid, r1 = r0 + 8, cc = nt * 8 + 2 * tig;
            float2 v0, v1;
            v0.x = o[mt][nt][0] * inv[mt][0];
            v0.y = o[mt][nt][1] * inv[mt][0];
            v1.x = o[mt][nt][2] * inv[mt][1];
            v1.y = o[mt][nt][3] * inv[mt][1];
            *reinterpret_cast<float2*>(dst + (size_t)r0 * 768 + cc) = v0;
            *reinterpret_cast<float2*>(dst + (size_t)r1 * 768 + cc) = v1;
        }
}

// ---------------------------------------------------------------------------
// Combine: ctx = tf32(O1 - O2_scaled), float4-wide.
// ---------------------------------------------------------------------------
#define CTX_F4 (M_ROWS * DIM_ / 4)   // 786432

__global__ __launch_bounds__(256)
void combine_o()
{
    int idx = blockIdx.x * 256 + threadIdx.x;
    if (idx >= CTX_F4) return;
    const float4* o1 = reinterpret_cast<const float4*>(g_od);
    const float4* o2 = reinterpret_cast<const float4*>(g_od + (size_t)M_ROWS * DIM_);
    float4 a = o1[idx], c = o2[idx];
    float4 r;
    r.x = to_tf32(a.x - c.x);
    r.y = to_tf32(a.y - c.y);
    r.z = to_tf32(a.z - c.z);
    r.w = to_tf32(a.w - c.w);
    reinterpret_cast<float4*>(g_ctx)[idx] = r;
}

// ---------------------------------------------------------------------------
// Launch
// ---------------------------------------------------------------------------
extern "C" void kernel_launch(void* const* d_in, const int* in_sizes, int n_in,
                              void* d_out, int out_size)
{
    const float* x      = (const float*)d_in[0];
    const float* Wq     = (const float*)d_in[1];
    const float* Wk     = (const float*)d_in[2];
    const float* Wv1    = (const float*)d_in[3];
    const float* Wv2    = (const float*)d_in[4];
    const float* lam_p  = (const float*)d_in[5];
    const float* Wo     = (const float*)d_in[6];
    const float* bo     = (const float*)d_in[7];
    float* out = (float*)d_out;

    float *gx, *gw, *gwo, *proj, *ctx;
    cudaGetSymbolAddress((void**)&gx,   g_x);
    cudaGetSymbolAddress((void**)&gw,   g_wqkv);
    cudaGetSymbolAddress((void**)&gwo,  g_wo);
    cudaGetSymbolAddress((void**)&proj, g_proj);
    cudaGetSymbolAddress((void**)&ctx,  g_ctx);

    cudaFuncSetAttribute(gemm_tf32, cudaFuncAttributeMaxDynamicSharedMemorySize,
                         GEMM_SMEM_BYTES);
    cudaFuncSetAttribute(attn_tc, cudaFuncAttributeMaxDynamicSharedMemorySize,
                         ATT_SMEM_BYTES);
    // request max smem carveout so 4 CTAs/SM fit (4 x 49.7 KB = 199 KB)
    cudaFuncSetAttribute(attn_tc, cudaFuncAttributePreferredSharedMemoryCarveout,
                         100);

    // tf32 pre-rounding + weight concat
    prep_tf32<<<(PREP_TOTAL + 255) / 256, 256>>>(x, Wq, Wk, Wv1, Wv2, Wo);

    // fused projections: one GEMM [4096 x 2560 x 768]; v1/v2 columns rounded
    gemm_tf32<<<dim3(PROJ_N / TBN, M_ROWS / TBM), 256, GEMM_SMEM_BYTES>>>(
        gx, gw, nullptr, proj, M_ROWS, PROJ_N, DIM_, OFF_V1);

    // RoPE + qk-norm over q+k (tf32-rounded output)
    {
        int vec = M_ROWS * 32;
        rope_norm<<<(vec * 32 + 255) / 256, 256>>>(proj, 32, PROJ_N, vec);
    }

    // tensor-core windowed attention: one side per block, 1024 blocks
    attn_tc<<<B_ * KV_ * 2 * SIDE_, 96, ATT_SMEM_BYTES>>>(lam_p);

    // differential combine
    combine_o<<<(CTX_F4 + 255) / 256, 256>>>();

    // output projection + bias
    gemm_tf32<<<dim3(DIM_ / TBN, M_ROWS / TBM), 256, GEMM_SMEM_BYTES>>>(
        ctx, gwo, bo, out, M_ROWS, DIM_, DIM_, 1 << 30);
}